// round 7
// baseline (speedup 1.0000x reference)
#include <cuda_runtime.h>
#include <math.h>

#define NT 256
#define RPB 8
#define NBLK 128
#define KC 32

typedef unsigned long long ull;

// ---------------- device scratch ----------------
__device__ float g_W0cat[152 * 512];   // [k][g]: rows 0..23 Wih0^T, 24..151 Whh0^T
__device__ float g_W1cat[256 * 512];   // [k][g]: rows 0..127 Wih1^T, 128..255 Whh1^T
__device__ float g_b0[512];
__device__ float g_b1[512];
__device__ float g_W1T[184 * 128];     // [k][u]
__device__ float g_W2s[128 * 128];     // [u][v] = W2[v][u]
__device__ float g_A1t[100 * 128];
__device__ float g_cy[100];
__device__ float g_ce[100];

// ---------------- prologue ----------------
__global__ void prologue_kernel(const float* __restrict__ W_ih0, const float* __restrict__ W_hh0,
                                const float* __restrict__ b_ih0, const float* __restrict__ b_hh0,
                                const float* __restrict__ W_ih1, const float* __restrict__ W_hh1,
                                const float* __restrict__ b_ih1, const float* __restrict__ b_hh1,
                                const float* __restrict__ W1,    const float* __restrict__ W2) {
    int tid = blockIdx.x * blockDim.x + threadIdx.x;
    int nth = gridDim.x * blockDim.x;

    for (int i = tid; i < 24 * 512; i += nth) {
        int k = i >> 9, g = i & 511;
        g_W0cat[i] = W_ih0[g * 24 + k];
    }
    for (int i = tid; i < 128 * 512; i += nth) {
        int k = i >> 9, g = i & 511;
        g_W0cat[(24 + k) * 512 + g]  = W_hh0[g * 128 + k];
        g_W1cat[k * 512 + g]         = W_ih1[g * 128 + k];
        g_W1cat[(128 + k) * 512 + g] = W_hh1[g * 128 + k];
    }
    for (int i = tid; i < 512; i += nth) {
        g_b0[i] = b_ih0[i] + b_hh0[i];
        g_b1[i] = b_ih1[i] + b_hh1[i];
    }
    for (int i = tid; i < 184 * 128; i += nth) {
        int k = i >> 7, u = i & 127;
        g_W1T[i] = W1[u * 184 + k];
    }
    for (int i = tid; i < 128 * 128; i += nth) {
        int u = i >> 7, v = i & 127;
        g_W2s[i] = W2[v * 128 + u];
    }
    for (int i = tid; i < 100 * 128; i += nth) {
        int t = i >> 7, u = i & 127;
        float acc = 0.f;
        #pragma unroll
        for (int j = 0; j < 8; j++) {
            float f = expf(-logf(10000.0f) * (float)j / 8.0f);
            float a = (float)t * f;
            acc += W1[u * 184 + 152 + j] * cosf(a);
            acc += W1[u * 184 + 160 + j] * sinf(a);
        }
        g_A1t[i] = acc;
    }
    if (tid == 0) {
        float ab = 1.0f;
        for (int t = 0; t < 100; t++) {
            float beta  = 1e-4f + (0.02f - 1e-4f) * (float)t / 99.0f;
            float alpha = 1.0f - beta;
            ab *= alpha;
            if (t == 0) {
                float p = sqrtf(ab) + 1e-8f;
                g_cy[0] = 1.0f / p;
                g_ce[0] = sqrtf(1.0f - ab) / p;
            } else {
                float inv = 1.0f / (sqrtf(alpha) + 1e-8f);
                g_cy[t] = inv;
                g_ce[t] = beta / (sqrtf(1.0f - ab) + 1e-8f) * inv;
            }
        }
    }
}

// ---------------- fast math helpers ----------------
__device__ __forceinline__ float sigf(float x) {
    float xc = fminf(fmaxf(x, -30.f), 30.f);
    return __fdividef(1.0f, 1.0f + __expf(-xc));
}
__device__ __forceinline__ float tanhf_fast(float x) {
    float xc = fminf(fmaxf(x, -15.f), 15.f);
    float e = __expf(2.0f * xc);
    return __fdividef(e - 1.0f, e + 1.0f);
}
__device__ __forceinline__ void ffma2(ull &d, ull a, ull b) {
    asm("fma.rn.f32x2 %0, %1, %2, %0;" : "+l"(d) : "l"(a), "l"(b));
}
__device__ __forceinline__ ull dup2(float x) {
    ull r;
    asm("mov.b64 %0, {%1, %1};" : "=l"(r) : "f"(x));
    return r;
}
__device__ __forceinline__ ull pack2(float lo, float hi) {
    ull r;
    asm("mov.b64 %0, {%1, %2};" : "=l"(r) : "f"(lo), "f"(hi));
    return r;
}
__device__ __forceinline__ float2 unpack2(ull v) {
    float2 r;
    asm("mov.b64 {%0, %1}, %2;" : "=f"(r.x), "=f"(r.y) : "l"(v));
    return r;
}

// ---------------- smem layout (floats) ----------------
#define SM_XV     0        // [280][8]: rows 0..7 x_t, 8..23 emb, 24..151 h0, 152..279 h1
#define SM_GATES  2240     // [8][512]
#define SM_STAGE  6336     // 2 x (KC*512) = 32768
#define SM_B0     39104    // 512
#define SM_B1     39616    // 512
#define SM_EMBR   40128    // [8][16]
#define SM_EMBT   40256    // [16][8]
#define SM_MH1T   40384    // [8][128] transposed
#define SM_A1     41408    // 12800
#define SM_W1Y    54208    // 128
#define SM_W3     54336    // 128
#define SM_BM2    54464    // 128
#define SM_XFT    54592    // 48
#define SM_HES    54640    // 32
#define SM_CY     54672    // 100
#define SM_CE     54772    // 100
#define SM_RED    54872    // 32
#define SM_TOTAL  54904
#define SMEM_BYTES (SM_TOTAL * 4)

// ---------------- staging helper ----------------
__device__ __forceinline__ void stage_chunk(float* sdst, const float* __restrict__ gsrc, int nf4) {
    unsigned sbase = (unsigned)__cvta_generic_to_shared(sdst);
    for (int i = threadIdx.x; i < nf4; i += NT) {
        asm volatile("cp.async.cg.shared.global [%0], [%1], 16;\n"
                     :: "r"(sbase + i * 16), "l"(gsrc + i * 4));
    }
    asm volatile("cp.async.commit_group;\n" ::: "memory");
}

__device__ __forceinline__ void barh(int half) {
    asm volatile("bar.sync %0, 128;" :: "r"(half + 1) : "memory");
}

// ---------------- LSTM GEMM: f32x2, paired-lane weight sharing (R4-proven) ----------------
__device__ __forceinline__ void lstm_gemm(const float* __restrict__ gW, int K,
                                          const float* __restrict__ xv, float* gates,
                                          float* stg, int g0, int r0g) {
    ull a00 = 0, a01 = 0, a10 = 0, a11 = 0, a20 = 0, a21 = 0, a30 = 0, a31 = 0;

    const int NC = (K + KC - 1) / KC;
    {
        int kc0 = (K < KC) ? K : KC;
        stage_chunk(stg, gW, kc0 * 128);
        if (NC > 1) {
            int kc1 = (K - KC < KC) ? (K - KC) : KC;
            stage_chunk(stg + KC * 512, gW + KC * 512, kc1 * 128);
        }
    }

    for (int c = 0; c < NC; c++) {
        if (c + 1 < NC) asm volatile("cp.async.wait_group 1;\n" ::: "memory");
        else            asm volatile("cp.async.wait_group 0;\n" ::: "memory");
        __syncthreads();

        const float* buf = stg + (c & 1) * (KC * 512);
        const int kbase = c * KC;
        int kc = K - kbase; if (kc > KC) kc = KC;

        #pragma unroll 8
        for (int kk = 0; kk < kc; kk++) {
            const ulonglong2 w = *reinterpret_cast<const ulonglong2*>(buf + (kk << 9) + g0);
            const float4 x = *reinterpret_cast<const float4*>(xv + ((kbase + kk) << 3) + r0g);
            ull d0 = dup2(x.x), d1 = dup2(x.y), d2 = dup2(x.z), d3 = dup2(x.w);
            ffma2(a00, w.x, d0); ffma2(a01, w.y, d0);
            ffma2(a10, w.x, d1); ffma2(a11, w.y, d1);
            ffma2(a20, w.x, d2); ffma2(a21, w.y, d2);
            ffma2(a30, w.x, d3); ffma2(a31, w.y, d3);
        }

        if (c == NC - 1) {
            *reinterpret_cast<ulonglong2*>(&gates[(r0g    ) * 512 + g0]) = make_ulonglong2(a00, a01);
            *reinterpret_cast<ulonglong2*>(&gates[(r0g + 1) * 512 + g0]) = make_ulonglong2(a10, a11);
            *reinterpret_cast<ulonglong2*>(&gates[(r0g + 2) * 512 + g0]) = make_ulonglong2(a20, a21);
            *reinterpret_cast<ulonglong2*>(&gates[(r0g + 3) * 512 + g0]) = make_ulonglong2(a30, a31);
        }
        __syncthreads();

        if (c + 2 < NC) {
            int kn = K - (c + 2) * KC; if (kn > KC) kn = KC;
            stage_chunk(stg + (c & 1) * (KC * 512), gW + (c + 2) * KC * 512, kn * 128);
        }
    }
}

// ---------------- main fused kernel ----------------
__global__ __launch_bounds__(NT, 1)
void fused_kernel(const float* __restrict__ x_hist, const float* __restrict__ x_future,
                  const float* __restrict__ y0, const int* __restrict__ turb_idx,
                  const float* __restrict__ init_noise, const float* __restrict__ turb_emb,
                  const float* __restrict__ b1m, const float* __restrict__ b2m,
                  const float* __restrict__ W3, const float* __restrict__ b3p,
                  float* __restrict__ out) {
    extern __shared__ float sm[];
    float* xv    = sm + SM_XV;
    float* gates = sm + SM_GATES;
    float* stg   = sm + SM_STAGE;
    float* b0s   = sm + SM_B0;
    float* b1s   = sm + SM_B1;
    float* embr  = sm + SM_EMBR;
    float* embT  = sm + SM_EMBT;
    float* mh1T  = sm + SM_MH1T;
    float* a1s   = sm + SM_A1;
    float* w1ys  = sm + SM_W1Y;
    float* w3s   = sm + SM_W3;
    float* bm2s  = sm + SM_BM2;
    float* xfT   = sm + SM_XFT;
    float* hes   = sm + SM_HES;
    float* cys   = sm + SM_CY;
    float* ces   = sm + SM_CE;
    float* red   = sm + SM_RED;

    const int tid  = threadIdx.x;
    const int brow = blockIdx.x * RPB;

    // ---- init ----
    for (int i = tid; i < 2048; i += NT) xv[192 + i] = 0.0f;   // h0, h1 = 0
    for (int i = tid; i < 512; i += NT) { b0s[i] = g_b0[i]; b1s[i] = g_b1[i]; }
    for (int i = tid; i < 12800; i += NT) a1s[i] = g_A1t[i];
    if (tid < 128) {
        int r = tid >> 4, k = tid & 15;
        embr[r * 16 + k] = turb_emb[turb_idx[brow + r] * 16 + k];
    }
    if (tid < 128) {
        w1ys[tid] = g_W1T[151 * 128 + tid];
        w3s[tid]  = W3[tid];
        bm2s[tid] = b2m[tid];
    }
    if (tid < 100) { cys[tid] = g_cy[tid]; ces[tid] = g_ce[tid]; }
    __syncthreads();
    if (tid < 128) {
        int k = tid >> 3, r = tid & 7;
        float v = embr[r * 16 + k];
        embT[k * 8 + r] = v;
        xv[(8 + k) * 8 + r] = v;   // constant emb part of in0
    }

    const int g0  = (tid >> 1) << 2;   // 4 gates (lane pairs share weight)
    const int r0g = (tid & 1) << 2;    // 4 rows
    const int uu  = tid & 127;
    const int r0c = (tid >> 7) << 2;   // combine rows

    float c0r[4] = {0.f, 0.f, 0.f, 0.f};
    float c1r[4] = {0.f, 0.f, 0.f, 0.f};

    // x_hist prefetch (one step ahead, registers)
    const int xk = tid & 7, xr = tid >> 3;
    float xnext = 0.f;
    if (tid < 64) xnext = __ldg(&x_hist[((brow + xr) * 96 + 0) * 8 + xk]);

    // =================== LSTM encoder ===================
    for (int t = 0; t < 96; t++) {
        if (tid < 64) {
            xv[xk * 8 + xr] = xnext;
            if (t + 1 < 96) xnext = __ldg(&x_hist[((brow + xr) * 96 + (t + 1)) * 8 + xk]);
        }
        lstm_gemm(g_W0cat, 152, xv, gates, stg, g0, r0g);
        #pragma unroll
        for (int ri = 0; ri < 4; ri++) {
            int r = r0c + ri;
            float gi = gates[r * 512 + uu]       + b0s[uu];
            float gf = gates[r * 512 + 128 + uu] + b0s[128 + uu];
            float gc = gates[r * 512 + 256 + uu] + b0s[256 + uu];
            float go = gates[r * 512 + 384 + uu] + b0s[384 + uu];
            float cc = sigf(gf) * c0r[ri] + sigf(gi) * tanhf_fast(gc);
            c0r[ri] = cc;
            xv[(24 + uu) * 8 + r] = sigf(go) * tanhf_fast(cc);
        }
        lstm_gemm(g_W1cat, 256, xv + 24 * 8, gates, stg, g0, r0g);
        #pragma unroll
        for (int ri = 0; ri < 4; ri++) {
            int r = r0c + ri;
            float gi = gates[r * 512 + uu]       + b1s[uu];
            float gf = gates[r * 512 + 128 + uu] + b1s[128 + uu];
            float gc = gates[r * 512 + 256 + uu] + b1s[256 + uu];
            float go = gates[r * 512 + 384 + uu] + b1s[384 + uu];
            float cc = sigf(gf) * c1r[ri] + sigf(gi) * tanhf_fast(gc);
            c1r[ri] = cc;
            xv[(152 + uu) * 8 + r] = sigf(go) * tanhf_fast(cc);
        }
        __syncthreads();
    }
    __syncthreads();
    // enc_out = xv rows 152..279, layout [128][8]

    // =================== AR + diffusion (two independent halves) ===================
    const int half = tid >> 7;
    const int local = tid & 127;
    const int r0d = half * 4;
    const float b3v = __ldg(&b3p[0]);

    // W2 pre-packed register pairs: w2p[i] = (W2[uu][2i], W2[uu][2i+1])
    ull w2p[64];
    #pragma unroll
    for (int i = 0; i < 64; i++)
        w2p[i] = pack2(__ldg(&g_W2s[((2 * i) << 7) + uu]),
                       __ldg(&g_W2s[((2 * i + 1) << 7) + uu]));

    const float w1yv = w1ys[uu];
    const float w3v  = w3s[uu];
    const float bm2v = bm2s[uu];

    float ypa[4];
    #pragma unroll
    for (int j = 0; j < 4; j++) ypa[j] = __ldg(&y0[brow + r0d + j]);

    const int wih = (tid >> 5) & 3;
    const int lane = tid & 31;

    for (int p = 0; p < 8; p++) {
        if (local < 24) {
            int k = local >> 2, rl = local & 3;
            xfT[half * 24 + k * 4 + rl] = __ldg(&x_future[(brow + r0d + rl) * 48 + p * 6 + k]);
        }
        if (local < 16) {
            int j = local & 7;
            float f = __expf(-logf(10000.0f) * (float)j / 8.0f);
            float a = (float)p * f;
            hes[half * 16 + local] = (local < 8) ? cosf(a) : sinf(a);
        }
        float yra[4];
        #pragma unroll
        for (int j = 0; j < 4; j++) yra[j] = __ldg(&init_noise[p * 1024 + brow + r0d + j]);
        barh(half);

        // ---- base (registers) ----
        float4 base = make_float4(0.f, 0.f, 0.f, 0.f);
        {
            #pragma unroll 8
            for (int k = 0; k < 128; k++) {
                float w = __ldg(&g_W1T[(k << 7) + uu]);
                const float4 h = *reinterpret_cast<const float4*>(&xv[(152 + k) * 8 + r0d]);
                base.x += w * h.x; base.y += w * h.y; base.z += w * h.z; base.w += w * h.w;
            }
            #pragma unroll
            for (int k = 0; k < 6; k++) {
                float w = __ldg(&g_W1T[((128 + k) << 7) + uu]);
                const float4 x = *reinterpret_cast<const float4*>(&xfT[half * 24 + k * 4]);
                base.x += w * x.x; base.y += w * x.y; base.z += w * x.z; base.w += w * x.w;
            }
            #pragma unroll
            for (int k = 0; k < 16; k++) {
                float w = __ldg(&g_W1T[((134 + k) << 7) + uu]);
                const float* ep = &embT[k * 8 + r0d];
                base.x += w * ep[0]; base.y += w * ep[1]; base.z += w * ep[2]; base.w += w * ep[3];
            }
            {
                float w = __ldg(&g_W1T[(150 << 7) + uu]);
                base.x += w * ypa[0]; base.y += w * ypa[1]; base.z += w * ypa[2]; base.w += w * ypa[3];
            }
            float hsum = 0.f;
            #pragma unroll
            for (int k = 0; k < 16; k++) hsum += __ldg(&g_W1T[((168 + k) << 7) + uu]) * hes[half * 16 + k];
            float bb = __ldg(&b1m[uu]) + hsum;
            base.x += bb; base.y += bb; base.z += bb; base.w += bb;
        }

        // ---- 100 diffusion steps ----
        for (int tt = 99; tt >= 0; tt--) {
            // stage 1: write transposed mh1T[row][u]
            {
                float av = a1s[tt * 128 + uu];
                mh1T[((r0d + 0) << 7) + uu] = fmaxf(base.x + yra[0] * w1yv + av, 0.f);
                mh1T[((r0d + 1) << 7) + uu] = fmaxf(base.y + yra[1] * w1yv + av, 0.f);
                mh1T[((r0d + 2) << 7) + uu] = fmaxf(base.z + yra[2] * w1yv + av, 0.f);
                mh1T[((r0d + 3) << 7) + uu] = fmaxf(base.w + yra[3] * w1yv + av, 0.f);
            }
            barh(half);

            // stage 2: u-packed f32x2 GEMV, no dup MOVs
            float e[4];
            {
                ull acc[4] = {0ULL, 0ULL, 0ULL, 0ULL};
                #pragma unroll 8
                for (int i = 0; i < 32; i++) {
                    ull wa = w2p[2 * i], wb = w2p[2 * i + 1];
                    #pragma unroll
                    for (int r = 0; r < 4; r++) {
                        const ulonglong2 h = *reinterpret_cast<const ulonglong2*>(
                            &mh1T[((r0d + r) << 7) + 4 * i]);
                        ffma2(acc[r], wa, h.x);
                        ffma2(acc[r], wb, h.y);
                    }
                }
                #pragma unroll
                for (int r = 0; r < 4; r++) {
                    float2 s = unpack2(acc[r]);
                    e[r] = fmaxf(s.x + s.y + bm2v, 0.f) * w3v;
                }
            }
            #pragma unroll
            for (int off = 16; off > 0; off >>= 1) {
                e[0] += __shfl_down_sync(0xffffffffu, e[0], off);
                e[1] += __shfl_down_sync(0xffffffffu, e[1], off);
                e[2] += __shfl_down_sync(0xffffffffu, e[2], off);
                e[3] += __shfl_down_sync(0xffffffffu, e[3], off);
            }
            if (lane == 0)
                *reinterpret_cast<float4*>(&red[half * 16 + wih * 4]) = make_float4(e[0], e[1], e[2], e[3]);
            barh(half);

            // y update (redundant per thread, registers)
            {
                const float4 q0 = *reinterpret_cast<const float4*>(&red[half * 16 + 0]);
                const float4 q1 = *reinterpret_cast<const float4*>(&red[half * 16 + 4]);
                const float4 q2 = *reinterpret_cast<const float4*>(&red[half * 16 + 8]);
                const float4 q3 = *reinterpret_cast<const float4*>(&red[half * 16 + 12]);
                float cy = cys[tt], ce = ces[tt];
                yra[0] = cy * yra[0] - ce * (b3v + q0.x + q1.x + q2.x + q3.x);
                yra[1] = cy * yra[1] - ce * (b3v + q0.y + q1.y + q2.y + q3.y);
                yra[2] = cy * yra[2] - ce * (b3v + q0.z + q1.z + q2.z + q3.z);
                yra[3] = cy * yra[3] - ce * (b3v + q0.w + q1.w + q2.w + q3.w);
            }
        }

        if (local < 4) {
            float v = (local == 0) ? yra[0] : (local == 1) ? yra[1] : (local == 2) ? yra[2] : yra[3];
            out[(brow + r0d + local) * 8 + p] = v;
        }
        #pragma unroll
        for (int j = 0; j < 4; j++) ypa[j] = yra[j];
    }
}

// ---------------- launch ----------------
extern "C" void kernel_launch(void* const* d_in, const int* in_sizes, int n_in,
                              void* d_out, int out_size) {
    const float* x_hist     = (const float*)d_in[0];
    const float* x_future   = (const float*)d_in[1];
    const float* y0         = (const float*)d_in[2];
    const int*   turb_idx   = (const int*)d_in[3];
    const float* init_noise = (const float*)d_in[5];
    const float* turb_emb   = (const float*)d_in[6];
    const float* W_ih0      = (const float*)d_in[7];
    const float* W_hh0      = (const float*)d_in[8];
    const float* b_ih0      = (const float*)d_in[9];
    const float* b_hh0      = (const float*)d_in[10];
    const float* W_ih1      = (const float*)d_in[11];
    const float* W_hh1      = (const float*)d_in[12];
    const float* b_ih1      = (const float*)d_in[13];
    const float* b_hh1      = (const float*)d_in[14];
    const float* W1         = (const float*)d_in[15];
    const float* b1m        = (const float*)d_in[16];
    const float* W2         = (const float*)d_in[17];
    const float* b2m        = (const float*)d_in[18];
    const float* W3         = (const float*)d_in[19];
    const float* b3         = (const float*)d_in[20];
    float* out = (float*)d_out;

    prologue_kernel<<<128, 256>>>(W_ih0, W_hh0, b_ih0, b_hh0,
                                  W_ih1, W_hh1, b_ih1, b_hh1, W1, W2);

    cudaFuncSetAttribute(fused_kernel, cudaFuncAttributeMaxDynamicSharedMemorySize, SMEM_BYTES);
    fused_kernel<<<NBLK, NT, SMEM_BYTES>>>(x_hist, x_future, y0, turb_idx, init_noise,
                                           turb_emb, b1m, b2m, W3, b3, out);
}

// round 8
// speedup vs baseline: 1.2568x; 1.2568x over previous
#include <cuda_runtime.h>
#include <math.h>

#define NT 256
#define RPB 8
#define NBLK 128
#define KC 32

typedef unsigned long long ull;

// ---------------- device scratch ----------------
__device__ float g_W0cat[152 * 512];   // [k][g]: rows 0..23 Wih0^T, 24..151 Whh0^T
__device__ float g_W1cat[256 * 512];   // [k][g]: rows 0..127 Wih1^T, 128..255 Whh1^T
__device__ float g_b0[512];
__device__ float g_b1[512];
__device__ float g_W1T[184 * 128];     // [k][u]
__device__ float g_W2s[128 * 128];     // [u][v] = W2[v][u]
__device__ float g_A1t[100 * 128];
__device__ float g_cy[100];
__device__ float g_ce[100];

// ---------------- prologue ----------------
__global__ void prologue_kernel(const float* __restrict__ W_ih0, const float* __restrict__ W_hh0,
                                const float* __restrict__ b_ih0, const float* __restrict__ b_hh0,
                                const float* __restrict__ W_ih1, const float* __restrict__ W_hh1,
                                const float* __restrict__ b_ih1, const float* __restrict__ b_hh1,
                                const float* __restrict__ W1,    const float* __restrict__ W2) {
    int tid = blockIdx.x * blockDim.x + threadIdx.x;
    int nth = gridDim.x * blockDim.x;

    for (int i = tid; i < 24 * 512; i += nth) {
        int k = i >> 9, g = i & 511;
        g_W0cat[i] = W_ih0[g * 24 + k];
    }
    for (int i = tid; i < 128 * 512; i += nth) {
        int k = i >> 9, g = i & 511;
        g_W0cat[(24 + k) * 512 + g]  = W_hh0[g * 128 + k];
        g_W1cat[k * 512 + g]         = W_ih1[g * 128 + k];
        g_W1cat[(128 + k) * 512 + g] = W_hh1[g * 128 + k];
    }
    for (int i = tid; i < 512; i += nth) {
        g_b0[i] = b_ih0[i] + b_hh0[i];
        g_b1[i] = b_ih1[i] + b_hh1[i];
    }
    for (int i = tid; i < 184 * 128; i += nth) {
        int k = i >> 7, u = i & 127;
        g_W1T[i] = W1[u * 184 + k];
    }
    for (int i = tid; i < 128 * 128; i += nth) {
        int u = i >> 7, v = i & 127;
        g_W2s[i] = W2[v * 128 + u];
    }
    for (int i = tid; i < 100 * 128; i += nth) {
        int t = i >> 7, u = i & 127;
        float acc = 0.f;
        #pragma unroll
        for (int j = 0; j < 8; j++) {
            float f = expf(-logf(10000.0f) * (float)j / 8.0f);
            float a = (float)t * f;
            acc += W1[u * 184 + 152 + j] * cosf(a);
            acc += W1[u * 184 + 160 + j] * sinf(a);
        }
        g_A1t[i] = acc;
    }
    if (tid == 0) {
        float ab = 1.0f;
        for (int t = 0; t < 100; t++) {
            float beta  = 1e-4f + (0.02f - 1e-4f) * (float)t / 99.0f;
            float alpha = 1.0f - beta;
            ab *= alpha;
            if (t == 0) {
                float p = sqrtf(ab) + 1e-8f;
                g_cy[0] = 1.0f / p;
                g_ce[0] = sqrtf(1.0f - ab) / p;
            } else {
                float inv = 1.0f / (sqrtf(alpha) + 1e-8f);
                g_cy[t] = inv;
                g_ce[t] = beta / (sqrtf(1.0f - ab) + 1e-8f) * inv;
            }
        }
    }
}

// ---------------- fast math helpers ----------------
__device__ __forceinline__ float sigf(float x) {
    float xc = fminf(fmaxf(x, -30.f), 30.f);
    return __fdividef(1.0f, 1.0f + __expf(-xc));
}
__device__ __forceinline__ float tanhf_fast(float x) {
    float xc = fminf(fmaxf(x, -15.f), 15.f);
    float e = __expf(2.0f * xc);
    return __fdividef(e - 1.0f, e + 1.0f);
}
__device__ __forceinline__ void ffma2(ull &d, ull a, ull b) {
    asm("fma.rn.f32x2 %0, %1, %2, %0;" : "+l"(d) : "l"(a), "l"(b));
}
__device__ __forceinline__ ull dup2(float x) {
    ull r;
    asm("mov.b64 %0, {%1, %1};" : "=l"(r) : "f"(x));
    return r;
}
__device__ __forceinline__ ull pack2(float lo, float hi) {
    ull r;
    asm("mov.b64 %0, {%1, %2};" : "=l"(r) : "f"(lo), "f"(hi));
    return r;
}
__device__ __forceinline__ float2 unpack2(ull v) {
    float2 r;
    asm("mov.b64 {%0, %1}, %2;" : "=f"(r.x), "=f"(r.y) : "l"(v));
    return r;
}

// ---------------- smem layout (floats) ----------------
#define SM_XV     0        // [280][8]: rows 0..7 x_t, 8..23 emb, 24..151 h0, 152..279 h1
#define SM_GATES  2240     // [8][512]
#define SM_STAGE  6336     // 2 x (KC*512) = 32768
#define SM_B0     39104    // 512
#define SM_B1     39616    // 512
#define SM_EMBR   40128    // [8][16]
#define SM_EMBT   40256    // [16][8]
#define SM_MH1    40384    // [128][8]
#define SM_W1Y    41408    // 128
#define SM_W3     41536    // 128
#define SM_BM2    41664    // 128
#define SM_XFT    41792    // 48
#define SM_HES    41840    // 32
#define SM_CY     41872    // 100
#define SM_CE     41972    // 100
#define SM_RED    42072    // 32
#define SM_A1     42112    // 12800
#define SM_TOTAL  54912
#define SMEM_BYTES (SM_TOTAL * 4)

// ---------------- staging helper ----------------
__device__ __forceinline__ void stage_chunk(float* sdst, const float* __restrict__ gsrc, int nf4) {
    unsigned sbase = (unsigned)__cvta_generic_to_shared(sdst);
    for (int i = threadIdx.x; i < nf4; i += NT) {
        asm volatile("cp.async.cg.shared.global [%0], [%1], 16;\n"
                     :: "r"(sbase + i * 16), "l"(gsrc + i * 4));
    }
    asm volatile("cp.async.commit_group;\n" ::: "memory");
}

__device__ __forceinline__ void barh(int half) {
    asm volatile("bar.sync %0, 128;" :: "r"(half + 1) : "memory");
}

// ---------------- LSTM GEMM: f32x2, paired-lane weight sharing (R4-proven) ----------------
__device__ __forceinline__ void lstm_gemm(const float* __restrict__ gW, int K,
                                          const float* __restrict__ xv, float* gates,
                                          float* stg, int g0, int r0g) {
    ull a00 = 0, a01 = 0, a10 = 0, a11 = 0, a20 = 0, a21 = 0, a30 = 0, a31 = 0;

    const int NC = (K + KC - 1) / KC;
    {
        int kc0 = (K < KC) ? K : KC;
        stage_chunk(stg, gW, kc0 * 128);
        if (NC > 1) {
            int kc1 = (K - KC < KC) ? (K - KC) : KC;
            stage_chunk(stg + KC * 512, gW + KC * 512, kc1 * 128);
        }
    }

    for (int c = 0; c < NC; c++) {
        if (c + 1 < NC) asm volatile("cp.async.wait_group 1;\n" ::: "memory");
        else            asm volatile("cp.async.wait_group 0;\n" ::: "memory");
        __syncthreads();

        const float* buf = stg + (c & 1) * (KC * 512);
        const int kbase = c * KC;
        int kc = K - kbase; if (kc > KC) kc = KC;

        #pragma unroll 8
        for (int kk = 0; kk < kc; kk++) {
            const ulonglong2 w = *reinterpret_cast<const ulonglong2*>(buf + (kk << 9) + g0);
            const float4 x = *reinterpret_cast<const float4*>(xv + ((kbase + kk) << 3) + r0g);
            ull d0 = dup2(x.x), d1 = dup2(x.y), d2 = dup2(x.z), d3 = dup2(x.w);
            ffma2(a00, w.x, d0); ffma2(a01, w.y, d0);
            ffma2(a10, w.x, d1); ffma2(a11, w.y, d1);
            ffma2(a20, w.x, d2); ffma2(a21, w.y, d2);
            ffma2(a30, w.x, d3); ffma2(a31, w.y, d3);
        }

        if (c == NC - 1) {
            *reinterpret_cast<ulonglong2*>(&gates[(r0g    ) * 512 + g0]) = make_ulonglong2(a00, a01);
            *reinterpret_cast<ulonglong2*>(&gates[(r0g + 1) * 512 + g0]) = make_ulonglong2(a10, a11);
            *reinterpret_cast<ulonglong2*>(&gates[(r0g + 2) * 512 + g0]) = make_ulonglong2(a20, a21);
            *reinterpret_cast<ulonglong2*>(&gates[(r0g + 3) * 512 + g0]) = make_ulonglong2(a30, a31);
        }
        __syncthreads();

        if (c + 2 < NC) {
            int kn = K - (c + 2) * KC; if (kn > KC) kn = KC;
            stage_chunk(stg + (c & 1) * (KC * 512), gW + (c + 2) * KC * 512, kn * 128);
        }
    }
}

// ---------------- main fused kernel ----------------
__global__ __launch_bounds__(NT, 1)
void fused_kernel(const float* __restrict__ x_hist, const float* __restrict__ x_future,
                  const float* __restrict__ y0, const int* __restrict__ turb_idx,
                  const float* __restrict__ init_noise, const float* __restrict__ turb_emb,
                  const float* __restrict__ b1m, const float* __restrict__ b2m,
                  const float* __restrict__ W3, const float* __restrict__ b3p,
                  float* __restrict__ out) {
    extern __shared__ float sm[];
    float* xv    = sm + SM_XV;
    float* gates = sm + SM_GATES;
    float* stg   = sm + SM_STAGE;
    float* b0s   = sm + SM_B0;
    float* b1s   = sm + SM_B1;
    float* embr  = sm + SM_EMBR;
    float* embT  = sm + SM_EMBT;
    float* mh1   = sm + SM_MH1;
    float* w1ys  = sm + SM_W1Y;
    float* w3s   = sm + SM_W3;
    float* bm2s  = sm + SM_BM2;
    float* xfT   = sm + SM_XFT;
    float* hes   = sm + SM_HES;
    float* cys   = sm + SM_CY;
    float* ces   = sm + SM_CE;
    float* red   = sm + SM_RED;
    float* a1s   = sm + SM_A1;

    const int tid  = threadIdx.x;
    const int brow = blockIdx.x * RPB;

    // ---- init ----
    for (int i = tid; i < 2048; i += NT) xv[192 + i] = 0.0f;   // h0, h1 = 0
    for (int i = tid; i < 512; i += NT) { b0s[i] = g_b0[i]; b1s[i] = g_b1[i]; }
    for (int i = tid; i < 12800; i += NT) a1s[i] = g_A1t[i];
    if (tid < 128) {
        int r = tid >> 4, k = tid & 15;
        embr[r * 16 + k] = turb_emb[turb_idx[brow + r] * 16 + k];
    }
    if (tid < 128) {
        w1ys[tid] = g_W1T[151 * 128 + tid];
        w3s[tid]  = W3[tid];
        bm2s[tid] = b2m[tid];
    }
    if (tid < 100) { cys[tid] = g_cy[tid]; ces[tid] = g_ce[tid]; }
    __syncthreads();
    if (tid < 128) {
        int k = tid >> 3, r = tid & 7;
        float v = embr[r * 16 + k];
        embT[k * 8 + r] = v;
        xv[(8 + k) * 8 + r] = v;   // constant emb part of in0
    }

    const int g0  = (tid >> 1) << 2;   // 4 gates (lane pairs share weight)
    const int r0g = (tid & 1) << 2;    // 4 rows
    const int uu  = tid & 127;
    const int r0c = (tid >> 7) << 2;   // combine rows

    float c0r[4] = {0.f, 0.f, 0.f, 0.f};
    float c1r[4] = {0.f, 0.f, 0.f, 0.f};

    // x_hist prefetch (one step ahead, registers)
    const int xk = tid & 7, xr = tid >> 3;
    float xnext = 0.f;
    if (tid < 64) xnext = __ldg(&x_hist[((brow + xr) * 96 + 0) * 8 + xk]);

    // =================== LSTM encoder ===================
    for (int t = 0; t < 96; t++) {
        if (tid < 64) {
            xv[xk * 8 + xr] = xnext;
            if (t + 1 < 96) xnext = __ldg(&x_hist[((brow + xr) * 96 + (t + 1)) * 8 + xk]);
        }
        lstm_gemm(g_W0cat, 152, xv, gates, stg, g0, r0g);
        #pragma unroll
        for (int ri = 0; ri < 4; ri++) {
            int r = r0c + ri;
            float gi = gates[r * 512 + uu]       + b0s[uu];
            float gf = gates[r * 512 + 128 + uu] + b0s[128 + uu];
            float gc = gates[r * 512 + 256 + uu] + b0s[256 + uu];
            float go = gates[r * 512 + 384 + uu] + b0s[384 + uu];
            float cc = sigf(gf) * c0r[ri] + sigf(gi) * tanhf_fast(gc);
            c0r[ri] = cc;
            xv[(24 + uu) * 8 + r] = sigf(go) * tanhf_fast(cc);
        }
        lstm_gemm(g_W1cat, 256, xv + 24 * 8, gates, stg, g0, r0g);
        #pragma unroll
        for (int ri = 0; ri < 4; ri++) {
            int r = r0c + ri;
            float gi = gates[r * 512 + uu]       + b1s[uu];
            float gf = gates[r * 512 + 128 + uu] + b1s[128 + uu];
            float gc = gates[r * 512 + 256 + uu] + b1s[256 + uu];
            float go = gates[r * 512 + 384 + uu] + b1s[384 + uu];
            float cc = sigf(gf) * c1r[ri] + sigf(gi) * tanhf_fast(gc);
            c1r[ri] = cc;
            xv[(152 + uu) * 8 + r] = sigf(go) * tanhf_fast(cc);
        }
        __syncthreads();
    }
    __syncthreads();
    // enc_out = xv rows 152..279, layout [128][8]

    // =================== AR + diffusion (two independent halves) ===================
    const int half = tid >> 7;
    const int local = tid & 127;
    const int r0d = half * 4;
    const float b3v = __ldg(&b3p[0]);

    // W2 column in registers: w2r[u] = W2[uu][u]   (R4-proven, no spill)
    float w2r[128];
    #pragma unroll
    for (int u = 0; u < 128; u++) w2r[u] = __ldg(&g_W2s[(u << 7) + uu]);

    const float w1yv = w1ys[uu];
    const float w3v  = w3s[uu];
    const float bm2v = bm2s[uu];

    float ypa[4];
    #pragma unroll
    for (int j = 0; j < 4; j++) ypa[j] = __ldg(&y0[brow + r0d + j]);

    const int wih = (tid >> 5) & 3;
    const int lane = tid & 31;

    for (int p = 0; p < 8; p++) {
        if (local < 24) {
            int k = local >> 2, rl = local & 3;
            xfT[half * 24 + k * 4 + rl] = __ldg(&x_future[(brow + r0d + rl) * 48 + p * 6 + k]);
        }
        if (local < 16) {
            int j = local & 7;
            float f = __expf(-logf(10000.0f) * (float)j / 8.0f);
            float a = (float)p * f;
            hes[half * 16 + local] = (local < 8) ? cosf(a) : sinf(a);
        }
        float yra[4];
        #pragma unroll
        for (int j = 0; j < 4; j++) yra[j] = __ldg(&init_noise[p * 1024 + brow + r0d + j]);
        barh(half);

        // ---- base (registers) ----
        float4 base = make_float4(0.f, 0.f, 0.f, 0.f);
        {
            #pragma unroll 8
            for (int k = 0; k < 128; k++) {
                float w = __ldg(&g_W1T[(k << 7) + uu]);
                const float4 h = *reinterpret_cast<const float4*>(&xv[(152 + k) * 8 + r0d]);
                base.x += w * h.x; base.y += w * h.y; base.z += w * h.z; base.w += w * h.w;
            }
            #pragma unroll
            for (int k = 0; k < 6; k++) {
                float w = __ldg(&g_W1T[((128 + k) << 7) + uu]);
                const float4 x = *reinterpret_cast<const float4*>(&xfT[half * 24 + k * 4]);
                base.x += w * x.x; base.y += w * x.y; base.z += w * x.z; base.w += w * x.w;
            }
            #pragma unroll
            for (int k = 0; k < 16; k++) {
                float w = __ldg(&g_W1T[((134 + k) << 7) + uu]);
                const float* ep = &embT[k * 8 + r0d];
                base.x += w * ep[0]; base.y += w * ep[1]; base.z += w * ep[2]; base.w += w * ep[3];
            }
            {
                float w = __ldg(&g_W1T[(150 << 7) + uu]);
                base.x += w * ypa[0]; base.y += w * ypa[1]; base.z += w * ypa[2]; base.w += w * ypa[3];
            }
            float hsum = 0.f;
            #pragma unroll
            for (int k = 0; k < 16; k++) hsum += __ldg(&g_W1T[((168 + k) << 7) + uu]) * hes[half * 16 + k];
            float bb = __ldg(&b1m[uu]) + hsum;
            base.x += bb; base.y += bb; base.z += bb; base.w += bb;
        }

        // ---- 100 diffusion steps ----
        for (int tt = 99; tt >= 0; tt--) {
            // stage 1
            {
                float av = a1s[tt * 128 + uu];
                float4 m;
                m.x = fmaxf(base.x + yra[0] * w1yv + av, 0.f);
                m.y = fmaxf(base.y + yra[1] * w1yv + av, 0.f);
                m.z = fmaxf(base.z + yra[2] * w1yv + av, 0.f);
                m.w = fmaxf(base.w + yra[3] * w1yv + av, 0.f);
                *reinterpret_cast<float4*>(&mh1[(uu << 3) + r0d]) = m;
            }
            barh(half);

            // stage 2: f32x2 GEMV (R4-proven)
            {
                ull acc01 = pack2(bm2v, bm2v);
                ull acc23 = acc01;
                #pragma unroll
                for (int u = 0; u < 128; u++) {
                    const ulonglong2 h = *reinterpret_cast<const ulonglong2*>(&mh1[(u << 3) + r0d]);
                    ull dw = dup2(w2r[u]);
                    ffma2(acc01, dw, h.x);
                    ffma2(acc23, dw, h.y);
                }
                float2 a01 = unpack2(acc01);
                float2 a23 = unpack2(acc23);
                float e0 = fmaxf(a01.x, 0.f) * w3v;
                float e1 = fmaxf(a01.y, 0.f) * w3v;
                float e2 = fmaxf(a23.x, 0.f) * w3v;
                float e3 = fmaxf(a23.y, 0.f) * w3v;
                #pragma unroll
                for (int off = 16; off > 0; off >>= 1) {
                    e0 += __shfl_down_sync(0xffffffffu, e0, off);
                    e1 += __shfl_down_sync(0xffffffffu, e1, off);
                    e2 += __shfl_down_sync(0xffffffffu, e2, off);
                    e3 += __shfl_down_sync(0xffffffffu, e3, off);
                }
                if (lane == 0)
                    *reinterpret_cast<float4*>(&red[half * 16 + wih * 4]) = make_float4(e0, e1, e2, e3);
            }
            barh(half);

            // y update (redundant per thread, registers)
            {
                const float4 q0 = *reinterpret_cast<const float4*>(&red[half * 16 + 0]);
                const float4 q1 = *reinterpret_cast<const float4*>(&red[half * 16 + 4]);
                const float4 q2 = *reinterpret_cast<const float4*>(&red[half * 16 + 8]);
                const float4 q3 = *reinterpret_cast<const float4*>(&red[half * 16 + 12]);
                float cy = cys[tt], ce = ces[tt];
                yra[0] = cy * yra[0] - ce * (b3v + q0.x + q1.x + q2.x + q3.x);
                yra[1] = cy * yra[1] - ce * (b3v + q0.y + q1.y + q2.y + q3.y);
                yra[2] = cy * yra[2] - ce * (b3v + q0.z + q1.z + q2.z + q3.z);
                yra[3] = cy * yra[3] - ce * (b3v + q0.w + q1.w + q2.w + q3.w);
            }
        }

        if (local < 4) {
            float v = (local == 0) ? yra[0] : (local == 1) ? yra[1] : (local == 2) ? yra[2] : yra[3];
            out[(brow + r0d + local) * 8 + p] = v;
        }
        #pragma unroll
        for (int j = 0; j < 4; j++) ypa[j] = yra[j];
    }
}

// ---------------- launch ----------------
extern "C" void kernel_launch(void* const* d_in, const int* in_sizes, int n_in,
                              void* d_out, int out_size) {
    const float* x_hist     = (const float*)d_in[0];
    const float* x_future   = (const float*)d_in[1];
    const float* y0         = (const float*)d_in[2];
    const int*   turb_idx   = (const int*)d_in[3];
    const float* init_noise = (const float*)d_in[5];
    const float* turb_emb   = (const float*)d_in[6];
    const float* W_ih0      = (const float*)d_in[7];
    const float* W_hh0      = (const float*)d_in[8];
    const float* b_ih0      = (const float*)d_in[9];
    const float* b_hh0      = (const float*)d_in[10];
    const float* W_ih1      = (const float*)d_in[11];
    const float* W_hh1      = (const float*)d_in[12];
    const float* b_ih1      = (const float*)d_in[13];
    const float* b_hh1      = (const float*)d_in[14];
    const float* W1         = (const float*)d_in[15];
    const float* b1m        = (const float*)d_in[16];
    const float* W2         = (const float*)d_in[17];
    const float* b2m        = (const float*)d_in[18];
    const float* W3         = (const float*)d_in[19];
    const float* b3         = (const float*)d_in[20];
    float* out = (float*)d_out;

    prologue_kernel<<<128, 256>>>(W_ih0, W_hh0, b_ih0, b_hh0,
                                  W_ih1, W_hh1, b_ih1, b_hh1, W1, W2);

    cudaFuncSetAttribute(fused_kernel, cudaFuncAttributeMaxDynamicSharedMemorySize, SMEM_BYTES);
    fused_kernel<<<NBLK, NT, SMEM_BYTES>>>(x_hist, x_future, y0, turb_idx, init_noise,
                                           turb_emb, b1m, b2m, W3, b3, out);
}